// round 14
// baseline (speedup 1.0000x reference)
#include <cuda_runtime.h>
#include <cuda_bf16.h>
#include <cuda_fp16.h>
#include <cstdint>

#define BATCH 2
#define CHW   64
#define DDIM  64
#define NTOK  8192
#define HW    1024
#define TDIM  8
#define NCTA  296        // 2 x 148 SMs, balanced persistent schedule
#define NITEMS 8192      // 128 q-tiles x 64 key blocks
#define NSLOT 4
#define ROWB  144        // 144 B smem row stride (72 halfwords)
#define QSCALE 0.180336880111120426f   // 0.125 * log2(e): softmax in base-2

// -------- global scratch (allocations forbidden) --------
__device__ __align__(256) __nv_bfloat16 g_q [BATCH * NTOK * DDIM];  // pre-scaled by QSCALE
__device__ __align__(256) __nv_bfloat16 g_k [BATCH * NTOK * DDIM];
__device__ __align__(256) __half        g_v [BATCH * NTOK * DDIM];
__device__ __align__(256) __half g_oth[NSLOT * BATCH * DDIM * NTOK]; // unnorm O partials f16 [slot][b][d][n]
__device__ __align__(256) float  g_l [NSLOT * BATCH * NTOK];         // l partials [slot][b][n]
__device__ __align__(256) __nv_bfloat16 g_wb[3 * DDIM * CHW];        // bf16 W (wq pre-scaled)
__device__ __align__(256) float         g_bias[3 * DDIM];            // bq pre-scaled

// ---------------- helpers ----------------
__device__ __forceinline__ uint32_t smem_u32(const void* p) {
    uint32_t a;
    asm("{ .reg .u64 t; cvta.to.shared.u64 t, %1; cvt.u32.u64 %0, t; }" : "=r"(a) : "l"(p));
    return a;
}
__device__ __forceinline__ void cp16(uint32_t saddr, const void* gaddr) {
    asm volatile("cp.async.cg.shared.global [%0], [%1], 16;" :: "r"(saddr), "l"(gaddr) : "memory");
}
#define CP_COMMIT() asm volatile("cp.async.commit_group;" ::: "memory")
#define CP_WAIT(n)  asm volatile("cp.async.wait_group %0;" :: "n"(n) : "memory")

__device__ __forceinline__ void ldsm_x4(uint32_t* r, uint32_t a) {
    asm volatile("ldmatrix.sync.aligned.m8n8.x4.shared.b16 {%0,%1,%2,%3}, [%4];"
                 : "=r"(r[0]), "=r"(r[1]), "=r"(r[2]), "=r"(r[3]) : "r"(a));
}
__device__ __forceinline__ void ldsm_x4_t(uint32_t* r, uint32_t a) {
    asm volatile("ldmatrix.sync.aligned.m8n8.x4.trans.shared.b16 {%0,%1,%2,%3}, [%4];"
                 : "=r"(r[0]), "=r"(r[1]), "=r"(r[2]), "=r"(r[3]) : "r"(a));
}
__device__ __forceinline__ void mma_bf16(float* c, const uint32_t* a, uint32_t b0, uint32_t b1) {
    asm volatile(
        "mma.sync.aligned.m16n8k16.row.col.f32.bf16.bf16.f32 "
        "{%0,%1,%2,%3}, {%4,%5,%6,%7}, {%8,%9}, {%0,%1,%2,%3};"
        : "+f"(c[0]), "+f"(c[1]), "+f"(c[2]), "+f"(c[3])
        : "r"(a[0]), "r"(a[1]), "r"(a[2]), "r"(a[3]), "r"(b0), "r"(b1));
}
__device__ __forceinline__ void mma_f16(float* c, const uint32_t* a, uint32_t b0, uint32_t b1) {
    asm volatile(
        "mma.sync.aligned.m16n8k16.row.col.f32.f16.f16.f32 "
        "{%0,%1,%2,%3}, {%4,%5,%6,%7}, {%8,%9}, {%0,%1,%2,%3};"
        : "+f"(c[0]), "+f"(c[1]), "+f"(c[2]), "+f"(c[3])
        : "r"(a[0]), "r"(a[1]), "r"(a[2]), "r"(a[3]), "r"(b0), "r"(b1));
}
__device__ __forceinline__ uint32_t pack_bf16(float lo, float hi) {
    uint32_t r;
    asm("cvt.rn.bf16x2.f32 %0, %1, %2;" : "=r"(r) : "f"(hi), "f"(lo));
    return r;
}
__device__ __forceinline__ uint32_t pack_f16(float lo, float hi) {
    uint32_t r;
    asm("cvt.rn.f16x2.f32 %0, %1, %2;" : "=r"(r) : "f"(hi), "f"(lo));
    return r;
}
__device__ __forceinline__ uint32_t ex2_h2(uint32_t a) {
    uint32_t r;
    asm("ex2.approx.f16x2 %0, %1;" : "=r"(r) : "r"(a));
    return r;
}
__device__ __forceinline__ uint32_t hadd2(uint32_t a, uint32_t b) {
    uint32_t r;
    asm("add.rn.f16x2 %0, %1, %2;" : "=r"(r) : "r"(a), "r"(b));
    return r;
}
__device__ __forceinline__ float2 h2_to_f2(uint32_t h) {
    __half2 v = *(__half2*)&h;
    return make_float2(__low2float(v), __high2float(v));
}
__device__ __forceinline__ float frcp(float x) {
    float r;
    asm("rcp.approx.ftz.f32 %0, %1;" : "=f"(r) : "f"(x));
    // one Newton step: r = r*(2 - x*r)  -> ~1 ulp
    r = r * (2.0f - x * r);
    return r;
}

// ---------------------------------------------------------------------------
// Kernel 0: one-time W/bias convert (wq, bq pre-scaled by QSCALE)
// ---------------------------------------------------------------------------
__global__ __launch_bounds__(256) void setup_kernel(
    const float* __restrict__ wq, const float* __restrict__ bq,
    const float* __restrict__ wk, const float* __restrict__ bk,
    const float* __restrict__ wv, const float* __restrict__ bv)
{
    int idx = blockIdx.x * 256 + threadIdx.x;
    if (idx < 3 * DDIM * CHW) {
        int m = idx >> 12, rc = idx & 4095;
        const float* W = (m == 0) ? wq : (m == 1) ? wk : wv;
        float sc = (m == 0) ? QSCALE : 1.0f;
        g_wb[idx] = __float2bfloat16_rn(W[rc] * sc);
    }
    if (idx < 3 * DDIM) {
        int m = idx >> 6;
        const float* Bp = (m == 0) ? bq : (m == 1) ? bk : bv;
        g_bias[idx] = Bp[idx & 63] * ((m == 0) ? QSCALE : 1.0f);
    }
}

// ---------------------------------------------------------------------------
// Kernel 1: QKV projection on HMMA. 64-token CTAs, grid 256, 128 threads,
// 2 CTAs/SM; x AND W pulled via cp.async.
// ---------------------------------------------------------------------------
#define PXF 0                    // fp32 x [64 c][68 n]       (17408 B)
#define PXB 17408                // bf16 x^T [64 n][72 c] 144B (9216 B)
#define PWB 26624                // bf16 W [3][64 d][72 c] 144B (27648 B)
#define PBI 54272                // fp32 bias [3][64]          (768 B)
#define PSM 55040

__global__ __launch_bounds__(128, 2) void proj_kernel(const float* __restrict__ x)
{
    extern __shared__ char psm[];
    float* xsf = (float*)psm;
    const uint32_t sb = smem_u32(psm);

    const int tid  = threadIdx.x;
    const int w    = tid >> 5;
    const int lane = tid & 31;
    const int g    = lane >> 2;
    const int tc   = lane & 3;
    const int b    = blockIdx.x >> 7;
    const int n0   = (blockIdx.x & 127) * 64;

    // W: exactly 1536 16-B chunks; bias: 48 chunks
    #pragma unroll
    for (int j = 0; j < 12; j++) {
        int c = tid + j * 128;                 // 0..1535
        int rrow = c >> 3, c8 = c & 7;
        cp16(sb + PWB + rrow * 144 + c8 * 16, (const char*)g_wb + c * 16);
    }
    if (tid < 48) cp16(sb + PBI + tid * 16, (const char*)g_bias + tid * 16);
    // x tile [64 c][64 n] fp32 (1024 chunks)
    #pragma unroll
    for (int j = 0; j < 8; j++) {
        int c = tid + j * 128;
        int r = c >> 4, c16 = c & 15;
        cp16(sb + PXF + r * 272 + c16 * 16,
             (const char*)x + (((size_t)(b * CHW + r)) * NTOK + n0) * 4 + c16 * 16);
    }
    CP_COMMIT();
    CP_WAIT(0);
    __syncthreads();

    // transpose-convert x -> bf16 [tok][c]
    {
        int n = tid >> 1, ch = (tid & 1) * 32;
        uint32_t u[16];
        #pragma unroll
        for (int j = 0; j < 16; j++)
            u[j] = pack_bf16(xsf[(ch + 2*j) * 68 + n], xsf[(ch + 2*j + 1) * 68 + n]);
        uint4* d4 = (uint4*)(psm + PXB + n * 144 + ch * 2);
        #pragma unroll
        for (int j = 0; j < 4; j++)
            d4[j] = make_uint4(u[4*j], u[4*j+1], u[4*j+2], u[4*j+3]);
    }
    __syncthreads();

    uint32_t af[4][4];
    {
        uint32_t arow = sb + PXB + (w * 16 + (lane & 15)) * 144 + (lane >> 4) * 16;
        #pragma unroll
        for (int kc = 0; kc < 4; kc++)
            ldsm_x4(af[kc], arow + kc * 32);
    }

    const float* biasf = (const float*)(psm + PBI);
    const uint32_t wrow = sb + PWB + (lane & 15) * 144 + (lane >> 4) * 16;

    #pragma unroll
    for (int m = 0; m < 3; m++) {
        float acc[4][2][4];
        #pragma unroll
        for (int i = 0; i < 4; i++)
            #pragma unroll
            for (int s2 = 0; s2 < 2; s2++)
                #pragma unroll
                for (int j = 0; j < 4; j++) acc[i][s2][j] = 0.f;

        #pragma unroll
        for (int nth = 0; nth < 4; nth++) {
            #pragma unroll
            for (int kc = 0; kc < 4; kc++) {
                uint32_t bf[4];
                ldsm_x4(bf, wrow + m * 9216 + nth * 16 * 144 + kc * 32);
                mma_bf16(acc[nth][0], af[kc], bf[0], bf[2]);
                mma_bf16(acc[nth][1], af[kc], bf[1], bf[3]);
            }
        }

        const size_t r0 = (size_t)(b * NTOK + n0 + w * 16 + g) * DDIM;
        const size_t r1 = r0 + 8 * DDIM;
        #pragma unroll
        for (int nth = 0; nth < 4; nth++) {
            #pragma unroll
            for (int s2 = 0; s2 < 2; s2++) {
                int d0 = nth * 16 + s2 * 8 + 2 * tc;
                float bb0 = biasf[m * 64 + d0], bb1 = biasf[m * 64 + d0 + 1];
                float v00 = acc[nth][s2][0] + bb0, v01 = acc[nth][s2][1] + bb1;
                float v10 = acc[nth][s2][2] + bb0, v11 = acc[nth][s2][3] + bb1;
                if (m < 2) {
                    __nv_bfloat16* dst = (m == 0) ? g_q : g_k;
                    *(uint32_t*)(dst + r0 + d0) = pack_bf16(v00, v01);
                    *(uint32_t*)(dst + r1 + d0) = pack_bf16(v10, v11);
                } else {
                    *(uint32_t*)(g_v + r0 + d0) = pack_f16(v00, v01);
                    *(uint32_t*)(g_v + r1 + d0) = pack_f16(v10, v11);
                }
            }
        }
    }
}

// ---------------------------------------------------------------------------
// Kernel 2: balanced persistent FA2 attention (unchanged from round 11).
// ---------------------------------------------------------------------------
#define SQ  0
#define SK  18432
#define SV  (18432 * 3)
#define SM_DYN (18432 * 5)

__device__ __forceinline__ void prefetch_kv(uint32_t sb, int item, int tid) {
    const int q  = item >> 6;
    const size_t kbase = (size_t)(q >> 6) * NTOK + (item & 63) * 128;
    const int p  = item & 1;
    const uint4* ks = (const uint4*)(g_k + kbase * DDIM);
    const uint4* vs = (const uint4*)(g_v + kbase * DDIM);
    #pragma unroll
    for (int c = tid, j = 0; j < 4; j++, c += 256) {
        int r = c >> 3, c8 = c & 7;
        uint32_t off = r * ROWB + c8 * 16;
        cp16(sb + SK + p * 18432 + off, ks + c);
        cp16(sb + SV + p * 18432 + off, vs + c);
    }
    CP_COMMIT();
}

__device__ __forceinline__ void flush_tile(
    char* smc, int qt, int bid, int tid, int w, int g, int tc,
    float (&Oc)[8][4], float ls0, float ls1)
{
    float a0 = ls0, a1 = ls1;
    a0 += __shfl_xor_sync(0xffffffffu, a0, 1);
    a0 += __shfl_xor_sync(0xffffffffu, a0, 2);
    a1 += __shfl_xor_sync(0xffffffffu, a1, 1);
    a1 += __shfl_xor_sync(0xffffffffu, a1, 2);
    int fb = qt >> 6, fn0 = (qt & 63) * 128;
    int c0 = (NCTA * (64 * qt + 1) - 1) >> 13;
    int slot = bid - c0;
    if (tc == 0) {
        float* lp = g_l + ((size_t)slot * BATCH + fb) * NTOK + fn0 + w * 16 + g;
        lp[0] = a0;
        lp[8] = a1;
    }
    __half* osm = (__half*)(smc + SQ);
    int r0 = w * 16 + g;
    #pragma unroll
    for (int nt = 0; nt < 8; nt++) {
        int d0 = nt * 8 + 2 * tc;
        osm[ d0      * 136 + r0    ] = __float2half_rn(Oc[nt][0]);
        osm[(d0 + 1) * 136 + r0    ] = __float2half_rn(Oc[nt][1]);
        osm[ d0      * 136 + r0 + 8] = __float2half_rn(Oc[nt][2]);
        osm[(d0 + 1) * 136 + r0 + 8] = __float2half_rn(Oc[nt][3]);
    }
    __syncthreads();
    __half* dst = g_oth + ((size_t)slot * BATCH + fb) * DDIM * NTOK + fn0;
    #pragma unroll
    for (int j = 0; j < 4; j++) {
        int c = tid + j * 256;
        int d = c >> 4, o16 = c & 15;
        uint4 v = *(uint4*)&osm[d * 136 + o16 * 8];
        *(uint4*)(dst + d * NTOK + o16 * 8) = v;
    }
}

__global__ __launch_bounds__(256, 2) void attn_kernel()
{
    extern __shared__ char smc[];
    const uint32_t sb = smem_u32(smc);

    const int bid  = blockIdx.x;
    const int tid  = threadIdx.x;
    const int w    = tid >> 5;
    const int lane = tid & 31;
    const int g    = lane >> 2;
    const int tc   = lane & 3;

    const int lo = (bid * NITEMS) / NCTA;
    const int hi = ((bid + 1) * NITEMS) / NCTA;

    prefetch_kv(sb, lo, tid);

    uint32_t qa[4][4];
    float Oc[8][4];
    float ls0, ls1;
    int qt = lo >> 6;

    {
        int b = qt >> 6, n0 = (qt & 63) * 128;
        const uint4* src = (const uint4*)(g_q + ((size_t)(b * NTOK + n0)) * DDIM);
        #pragma unroll
        for (int c = tid, j = 0; j < 4; j++, c += 256) {
            int r = c >> 3, c8 = c & 7;
            *(uint4*)(smc + SQ + r * ROWB + c8 * 16) = src[c];
        }
    }
    __syncthreads();
    {
        uint32_t rowaddr = sb + SQ + (w * 16 + (lane & 15)) * ROWB + (lane >> 4) * 16;
        #pragma unroll
        for (int kc = 0; kc < 4; kc++) ldsm_x4(qa[kc], rowaddr + kc * 32);
    }
    #pragma unroll
    for (int i = 0; i < 8; i++)
        #pragma unroll
        for (int j = 0; j < 4; j++) Oc[i][j] = 0.f;
    ls0 = ls1 = 0.f;

    for (int item = lo; item < hi; item++) {
        CP_WAIT(0);
        __syncthreads();
        if (item + 1 < hi) prefetch_kv(sb, item + 1, tid);

        const int q = item >> 6;
        if (q != qt) {
            flush_tile(smc, qt, bid, tid, w, g, tc, Oc, ls0, ls1);
            __syncthreads();
            {
                int b = q >> 6, n0 = (q & 63) * 128;
                const uint4* src = (const uint4*)(g_q + ((size_t)(b * NTOK + n0)) * DDIM);
                #pragma unroll
                for (int c = tid, j = 0; j < 4; j++, c += 256) {
                    int r = c >> 3, c8 = c & 7;
                    *(uint4*)(smc + SQ + r * ROWB + c8 * 16) = src[c];
                }
            }
            __syncthreads();
            {
                uint32_t rowaddr = sb + SQ + (w * 16 + (lane & 15)) * ROWB + (lane >> 4) * 16;
                #pragma unroll
                for (int kc = 0; kc < 4; kc++) ldsm_x4(qa[kc], rowaddr + kc * 32);
            }
            #pragma unroll
            for (int i = 0; i < 8; i++)
                #pragma unroll
                for (int j = 0; j < 4; j++) Oc[i][j] = 0.f;
            ls0 = ls1 = 0.f;
            qt = q;
        }

        const int p = item & 1;
        const uint32_t kb = sb + SK + p * 18432;
        const uint32_t vb = sb + SV + p * 18432;
        const uint32_t lrow = (lane & 15) * ROWB + (lane >> 4) * 16;

        uint32_t s0a = 0u, s1a = 0u;
        #pragma unroll
        for (int h = 0; h < 2; h++) {
            float S[8][4];
            #pragma unroll
            for (int nth = 0; nth < 4; nth++) {
                #pragma unroll
                for (int j = 0; j < 4; j++) { S[2*nth][j] = 0.f; S[2*nth+1][j] = 0.f; }
                #pragma unroll
                for (int kc = 0; kc < 4; kc++) {
                    uint32_t kf[4];
                    ldsm_x4(kf, kb + (h * 4 + nth) * 16 * ROWB + lrow + kc * 32);
                    mma_bf16(S[2*nth],     qa[kc], kf[0], kf[2]);
                    mma_bf16(S[2*nth + 1], qa[kc], kf[1], kf[3]);
                }
            }
            #pragma unroll
            for (int kc2 = 0; kc2 < 4; kc2++) {
                uint32_t pab[4];
                pab[0] = ex2_h2(pack_f16(S[2*kc2][0],   S[2*kc2][1]));
                pab[1] = ex2_h2(pack_f16(S[2*kc2][2],   S[2*kc2][3]));
                pab[2] = ex2_h2(pack_f16(S[2*kc2+1][0], S[2*kc2+1][1]));
                pab[3] = ex2_h2(pack_f16(S[2*kc2+1][2], S[2*kc2+1][3]));
                s0a = hadd2(hadd2(s0a, pab[0]), pab[2]);
                s1a = hadd2(hadd2(s1a, pab[1]), pab[3]);
                #pragma unroll
                for (int ntp = 0; ntp < 4; ntp++) {
                    uint32_t vf[4];
                    ldsm_x4_t(vf, vb + (h * 4 + kc2) * 16 * ROWB + lrow + ntp * 32);
                    mma_f16(Oc[2*ntp],     pab, vf[0], vf[1]);
                    mma_f16(Oc[2*ntp + 1], pab, vf[2], vf[3]);
                }
            }
        }
        {
            float2 f0 = h2_to_f2(s0a), f1 = h2_to_f2(s1a);
            ls0 += f0.x + f0.y;
            ls1 += f1.x + f1.y;
        }
    }

    __syncthreads();
    flush_tile(smc, qt, bid, tid, w, g, tc, Oc, ls0, ls1);
}

// ---------------------------------------------------------------------------
// Kernel 3: combine slots + normalize + t-reduce. MLP-maximized: all 32 l
// loads batched, then all 32 O loads batched; reciprocal via rcp+NR.
// ---------------------------------------------------------------------------
__global__ __launch_bounds__(256) void reduce_kernel(float* __restrict__ out)
{
    int idx = blockIdx.x * 256 + threadIdx.x;     // pair index, 0 .. 65535
    int yx = (idx & 511) * 2;
    int d  = (idx >> 9) & 63;
    int b  = idx >> 15;
    const size_t SLOT_O = (size_t)BATCH * DDIM * NTOK;
    const size_t SLOT_L = (size_t)BATCH * NTOK;
    const __half* o0 = g_oth + ((size_t)b * DDIM + d) * NTOK + yx;
    const float*  l0 = g_l   + (size_t)b * NTOK + yx;

    // batch 1: all 32 l float2 loads (independent)
    float2 lraw[8][4];
    #pragma unroll
    for (int t = 0; t < TDIM; t++)
        #pragma unroll
        for (int s = 0; s < NSLOT; s++)
            lraw[t][s] = *(const float2*)(l0 + s * SLOT_L + t * HW);

    // batch 2: all 32 O half2 loads (independent)
    __half2 hv[8][4];
    #pragma unroll
    for (int t = 0; t < TDIM; t++)
        #pragma unroll
        for (int s = 0; s < NSLOT; s++)
            hv[t][s] = *(const __half2*)(o0 + s * SLOT_O + t * HW);

    float2 acc = make_float2(0.f, 0.f);
    #pragma unroll
    for (int t = 0; t < TDIM; t++) {
        float lx = lraw[t][0].x + lraw[t][1].x + lraw[t][2].x + lraw[t][3].x;
        float ly = lraw[t][0].y + lraw[t][1].y + lraw[t][2].y + lraw[t][3].y;
        float rx = frcp(lx), ry = frcp(ly);
        float2 f0 = __half22float2(hv[t][0]);
        float2 f1 = __half22float2(hv[t][1]);
        float2 f2 = __half22float2(hv[t][2]);
        float2 f3 = __half22float2(hv[t][3]);
        acc.x += (f0.x + f1.x + f2.x + f3.x) * rx;
        acc.y += (f0.y + f1.y + f2.y + f3.y) * ry;
    }
    *(float2*)(out + ((size_t)(b * DDIM + d)) * HW + yx) = acc;
}

// ---------------------------------------------------------------------------
extern "C" void kernel_launch(void* const* d_in, const int* in_sizes, int n_in,
                              void* d_out, int out_size)
{
    const float* x  = (const float*)d_in[0];
    const float* wq = (const float*)d_in[1];
    const float* bq = (const float*)d_in[2];
    const float* wk = (const float*)d_in[3];
    const float* bk = (const float*)d_in[4];
    const float* wv = (const float*)d_in[5];
    const float* bv = (const float*)d_in[6];

    cudaFuncSetAttribute(proj_kernel,
                         cudaFuncAttributeMaxDynamicSharedMemorySize, PSM);
    cudaFuncSetAttribute(attn_kernel,
                         cudaFuncAttributeMaxDynamicSharedMemorySize, SM_DYN);

    setup_kernel<<<48, 256>>>(wq, bq, wk, bk, wv, bv);
    proj_kernel<<<BATCH * (NTOK / 64), 128, PSM>>>(x);
    attn_kernel<<<NCTA, 256, SM_DYN>>>();
    reduce_kernel<<<BATCH * DDIM * HW / 512, 256>>>((float*)d_out);
}